// round 13
// baseline (speedup 1.0000x reference)
#include <cuda_runtime.h>

#define NB 8
#define NL 4096
#define NK 16
#define ND 128

// scratch (allocation-free rule -> __device__ globals)
__device__ int   g_nbr[NB * NL * NK];
__device__ float g_xs[NB * NL];
__device__ float g_ys[NB * NL];
__device__ float g_zs[NB * NL];
__device__ int   g_oi[NB * NL];

// ---------------------------------------------------------------------------
// u64-key top-16 insert (sorted ascending, median split). Key =
// (dist_bits << 32) | orig_idx : unsigned compare = exact lexicographic
// (d, idx) = jax.lax.top_k order. Order-independent selection.
// ---------------------------------------------------------------------------
__device__ __forceinline__ void kins(unsigned long long (&ks)[NK],
                                     unsigned long long nk)
{
    if (nk < ks[7]) {
#pragma unroll
        for (int i = 15; i > 8; --i) ks[i] = ks[i - 1];
        ks[8] = ks[7];
        unsigned long long c = nk;
#pragma unroll
        for (int i = 0; i < 8; ++i) {
            if (c < ks[i]) { unsigned long long t = ks[i]; ks[i] = c; c = t; }
        }
    } else {
        unsigned long long c = nk;
#pragma unroll
        for (int i = 8; i < 16; ++i) {
            if (c < ks[i]) { unsigned long long t = ks[i]; ks[i] = c; c = t; }
        }
    }
}

// ---------------------------------------------------------------------------
// Kernel 0: per-batch bitonic sort of (x, idx) -> sorted SoA coordinate
// arrays + original-index map. One block per batch, keys in smem.
// ---------------------------------------------------------------------------
__global__ __launch_bounds__(1024)
void sort_kernel(const float* __restrict__ frame)
{
    __shared__ unsigned long long sk[NL];
    const int b   = blockIdx.x;
    const int tid = threadIdx.x;
    const float* fb = frame + (size_t)b * NL * 12;

    for (int i = tid; i < NL; i += 1024) {
        unsigned fbits = __float_as_uint(fb[(size_t)i * 12]);   // x coord
        // order-preserving map: negatives flip all bits, positives set sign
        unsigned m = fbits ^ ((unsigned)((int)fbits >> 31) | 0x80000000u);
        sk[i] = ((unsigned long long)m << 32) | (unsigned)i;
    }
    __syncthreads();

    for (int k = 2; k <= NL; k <<= 1) {
        for (int j = k >> 1; j > 0; j >>= 1) {
            for (int i = tid; i < NL; i += 1024) {
                const int ixj = i ^ j;
                if (ixj > i) {
                    unsigned long long a = sk[i], c = sk[ixj];
                    const bool up = ((i & k) == 0);
                    if ((a > c) == up) { sk[i] = c; sk[ixj] = a; }
                }
            }
            __syncthreads();
        }
    }

    for (int i = tid; i < NL; i += 1024) {
        const int oi = (int)(unsigned)sk[i];
        const float* p = fb + (size_t)oi * 12;
        g_xs[b * NL + i] = p[0];
        g_ys[b * NL + i] = p[1];
        g_zs[b * NL + i] = p[2];
        g_oi[b * NL + i] = oi;
    }
}

// ---------------------------------------------------------------------------
// Kernel 1: exact 16-NN via sorted-x window expansion. One thread per query
// (= per sorted position). Two pointers expand outward; a side dies when its
// dx^2 strictly exceeds tau (16th-best distance) — every further point on
// that side is strictly worse. Exact unfused rn arithmetic; u64 keys.
// ---------------------------------------------------------------------------
__global__ __launch_bounds__(256)
void knn_sorted_kernel(const float* __restrict__ frame,
                       float* __restrict__ eucl_out)
{
    const int g = blockIdx.x * 256 + threadIdx.x;    // 0..NB*NL-1
    const int b = g >> 12;                           // / NL
    const int p = g & (NL - 1);

    const float* xs = g_xs + b * NL;
    const float* ys = g_ys + b * NL;
    const float* zs = g_zs + b * NL;
    const int*   oi = g_oi + b * NL;

    const float cx = xs[p], cy = ys[p], cz = zs[p];
    const int   q  = oi[p];

    unsigned long long ks[NK];
#pragma unroll
    for (int i = 0; i < NK; ++i) ks[i] = ~0ull;

    // self: d = 0 exactly
    kins(ks, (unsigned long long)(unsigned)q);

    // tau = distance of current 16th (NaN while list not full -> no pruning:
    // float '>' with NaN is false)
    float taud = __uint_as_float((unsigned)(ks[NK - 1] >> 32));

    int lo = p - 1, hi = p + 1;

    while (true) {
        float axl = 3.0e38f, axr = 3.0e38f;
        if (lo >= 0) {
            float t = __fadd_rn(cx, -xs[lo]);
            axl = __fmul_rn(t, t);
            if (axl > taud) { lo = -1; axl = 3.0e38f; }   // kill left side
        }
        if (hi < NL) {
            float t = __fadd_rn(cx, -xs[hi]);
            axr = __fmul_rn(t, t);
            if (axr > taud) { hi = NL; axr = 3.0e38f; }   // kill right side
        }
        if (lo < 0 && hi >= NL) break;

        const bool left = (axl <= axr);                   // dead side = 3e38
        const int  pos  = left ? lo : hi;

        const float dx = __fadd_rn(cx, -xs[pos]);
        const float dy = __fadd_rn(cy, -ys[pos]);
        const float dz = __fadd_rn(cz, -zs[pos]);
        const float d  = __fadd_rn(__fadd_rn(__fmul_rn(dx, dx), __fmul_rn(dy, dy)),
                                   __fmul_rn(dz, dz));
        const unsigned long long nk =
            ((unsigned long long)__float_as_uint(d) << 32) | (unsigned)oi[pos];
        if (nk < ks[NK - 1]) {
            kins(ks, nk);
            taud = __uint_as_float((unsigned)(ks[NK - 1] >> 32));
        }
        if (left) lo--; else hi++;
    }

    // ---- outputs: neighbor indices + rotated deltas ----------------------
    const float* fq = frame + ((size_t)b * NL + q) * 12;
    float R[3][3];
#pragma unroll
    for (int c = 0; c < 3; c++)
#pragma unroll
        for (int r = 0; r < 3; r++)
            R[c][r] = fq[3 + c * 3 + r];

    const size_t base = ((size_t)b * NL + q) * NK;

    // packed neighbor-index stores (4 x int4, 64B-aligned)
    int4* nb4 = (int4*)(g_nbr + base);
#pragma unroll
    for (int kk = 0; kk < 4; ++kk)
        nb4[kk] = make_int4((int)(unsigned)ks[4 * kk],
                            (int)(unsigned)ks[4 * kk + 1],
                            (int)(unsigned)ks[4 * kk + 2],
                            (int)(unsigned)ks[4 * kk + 3]);

    // eucl: 4 neighbors (12 floats = 3 float4) per chunk, 4 chunks
    float4* eo = (float4*)(eucl_out + base * 3);
#pragma unroll
    for (int kk = 0; kk < 4; ++kk) {
        float e[12];
#pragma unroll
        for (int u = 0; u < 4; ++u) {
            const int n = (int)(unsigned)ks[4 * kk + u];
            const float* fn = frame + ((size_t)b * NL + n) * 12;
            float d0 = fn[0] - cx;
            float d1 = fn[1] - cy;
            float d2 = fn[2] - cz;
            e[3 * u + 0] = d0 * R[0][0] + d1 * R[1][0] + d2 * R[2][0];
            e[3 * u + 1] = d0 * R[0][1] + d1 * R[1][1] + d2 * R[2][1];
            e[3 * u + 2] = d0 * R[0][2] + d1 * R[1][2] + d2 * R[2][2];
        }
        eo[3 * kk + 0] = make_float4(e[0], e[1], e[2],  e[3]);
        eo[3 * kk + 1] = make_float4(e[4], e[5], e[6],  e[7]);
        eo[3 * kk + 2] = make_float4(e[8], e[9], e[10], e[11]);
    }
}

// ---------------------------------------------------------------------------
// Kernel 2: attribute gather (best measured config: 4 rows/warp, 8 lanes per
// row, 4 float4 per lane -> ~44us, at the store ceiling).
// ---------------------------------------------------------------------------
__global__ __launch_bounds__(256, 8)
void gather_kernel(const float* __restrict__ attr,
                   float* __restrict__ gout)
{
    const int warp = (blockIdx.x * 256 + threadIdx.x) >> 5;
    const int lane = threadIdx.x & 31;
    const int row  = warp * 4 + (lane >> 3);      // 4 rows per warp
    const int l8   = lane & 7;

    const int b = row / (NL * NK);
    const int n = g_nbr[row];

    const float4* src = (const float4*)(attr + ((size_t)b * NL + n) * ND);
    float4*       dst = (float4*)(gout + (size_t)row * ND);

    float4 v0 = src[l8];
    float4 v1 = src[l8 + 8];
    float4 v2 = src[l8 + 16];
    float4 v3 = src[l8 + 24];
    dst[l8]      = v0;
    dst[l8 + 8]  = v1;
    dst[l8 + 16] = v2;
    dst[l8 + 24] = v3;
}

extern "C" void kernel_launch(void* const* d_in, const int* in_sizes, int n_in,
                              void* d_out, int out_size)
{
    const float* frame = (const float*)d_in[0];
    const float* attr  = (const float*)d_in[1];
    if (in_sizes[0] != NB * NL * 12) {
        frame = (const float*)d_in[1];
        attr  = (const float*)d_in[0];
    }

    float* eucl = (float*)d_out;                          // B*L*K*3 floats
    float* gath = (float*)d_out + (size_t)NB * NL * NK * 3;

    sort_kernel<<<NB, 1024>>>(frame);

    const int nq = NB * NL;                               // 32768 queries
    knn_sorted_kernel<<<nq / 256, 256>>>(frame, eucl);

    const int rows = NB * NL * NK;                        // 524288
    gather_kernel<<<rows / 32, 256>>>(attr, gath);        // 4 rows/warp
}

// round 14
// speedup vs baseline: 2.4497x; 2.4497x over previous
#include <cuda_runtime.h>

#define NB 8
#define NL 4096
#define NK 16
#define ND 128

#define QPB 64            // queries per block (sorted-consecutive)
#define TPB 128           // 2 threads per query
#define TILE 1024
#define NTILES (NL / TILE)
#define BCAP 24           // per-thread candidate buffer capacity

// scratch (allocation-free rule -> __device__ globals)
__device__ int   g_nbr[NB * NL * NK];
__device__ float g_xs[NB * NL];
__device__ float g_ys[NB * NL];
__device__ float g_zs[NB * NL];
__device__ int   g_oi[NB * NL];

#define INF_KEY 0x7F800000FFFFFFFFull   // (+inf dist, max idx)

// ---------------------------------------------------------------------------
// u64-key top-16 insert (sorted ascending, median split). Key =
// (dist_bits<<32)|orig_idx: unsigned compare = exact lexicographic (d, idx)
// = jax.lax.top_k order. Order-independent.
// ---------------------------------------------------------------------------
__device__ __forceinline__ void kins(unsigned long long (&ks)[NK],
                                     unsigned long long nk)
{
    if (nk < ks[7]) {
#pragma unroll
        for (int i = 15; i > 8; --i) ks[i] = ks[i - 1];
        ks[8] = ks[7];
        unsigned long long c = nk;
#pragma unroll
        for (int i = 0; i < 8; ++i) {
            if (c < ks[i]) { unsigned long long t = ks[i]; ks[i] = c; c = t; }
        }
    } else {
        unsigned long long c = nk;
#pragma unroll
        for (int i = 8; i < 16; ++i) {
            if (c < ks[i]) { unsigned long long t = ks[i]; ks[i] = c; c = t; }
        }
    }
}

__device__ __forceinline__ unsigned long long pack2(float lo, float hi)
{
    unsigned long long r;
    asm("mov.b64 %0, {%1, %2};" : "=l"(r) : "f"(lo), "f"(hi));
    return r;
}

// packed squared-distance for one PAIR (exact unfused IEEE rn per lane)
__device__ __forceinline__ void dist2(unsigned long long x2, unsigned long long y2,
                                      unsigned long long z2,
                                      unsigned long long ncx2, unsigned long long ncy2,
                                      unsigned long long ncz2,
                                      float& d0, float& d1)
{
    unsigned long long dx2, dy2, dz2, m0, m1, m2, s0, dd;
    asm("add.rn.f32x2 %0, %1, %2;" : "=l"(dx2) : "l"(x2), "l"(ncx2));
    asm("add.rn.f32x2 %0, %1, %2;" : "=l"(dy2) : "l"(y2), "l"(ncy2));
    asm("add.rn.f32x2 %0, %1, %2;" : "=l"(dz2) : "l"(z2), "l"(ncz2));
    asm("mul.rn.f32x2 %0, %1, %2;" : "=l"(m0) : "l"(dx2), "l"(dx2));
    asm("mul.rn.f32x2 %0, %1, %2;" : "=l"(m1) : "l"(dy2), "l"(dy2));
    asm("mul.rn.f32x2 %0, %1, %2;" : "=l"(m2) : "l"(dz2), "l"(dz2));
    asm("add.rn.f32x2 %0, %1, %2;" : "=l"(s0) : "l"(m0), "l"(m1));
    asm("add.rn.f32x2 %0, %1, %2;" : "=l"(dd) : "l"(s0), "l"(m2));
    asm("mov.b64 {%0, %1}, %2;" : "=f"(d0), "=f"(d1) : "l"(dd));
}

// ---------------------------------------------------------------------------
// Kernel 0: per-batch bitonic sort of (x, idx) -> sorted SoA arrays (proven).
// ---------------------------------------------------------------------------
__global__ __launch_bounds__(1024)
void sort_kernel(const float* __restrict__ frame)
{
    __shared__ unsigned long long sk[NL];
    const int b   = blockIdx.x;
    const int tid = threadIdx.x;
    const float* fb = frame + (size_t)b * NL * 12;

    for (int i = tid; i < NL; i += 1024) {
        unsigned fbits = __float_as_uint(fb[(size_t)i * 12]);
        unsigned m = fbits ^ ((unsigned)((int)fbits >> 31) | 0x80000000u);
        sk[i] = ((unsigned long long)m << 32) | (unsigned)i;
    }
    __syncthreads();

    for (int k = 2; k <= NL; k <<= 1) {
        for (int j = k >> 1; j > 0; j >>= 1) {
            for (int i = tid; i < NL; i += 1024) {
                const int ixj = i ^ j;
                if (ixj > i) {
                    unsigned long long a = sk[i], c = sk[ixj];
                    const bool up = ((i & k) == 0);
                    if ((a > c) == up) { sk[i] = c; sk[ixj] = a; }
                }
            }
            __syncthreads();
        }
    }

    for (int i = tid; i < NL; i += 1024) {
        const int oi = (int)(unsigned)sk[i];
        const float* p = fb + (size_t)oi * 12;
        g_xs[b * NL + i] = p[0];
        g_ys[b * NL + i] = p[1];
        g_zs[b * NL + i] = p[2];
        g_oi[b * NL + i] = oi;
    }
}

// ---------------------------------------------------------------------------
// Kernel 1: exact 16-NN, tile-windowed. Block = 64 sorted-consecutive
// queries. Scan own 1024-tile (R6 inner economics), then vote in the
// remaining tiles by x-edge pruning (conservative => exact).
// ---------------------------------------------------------------------------
__global__ __launch_bounds__(TPB, 4)
void knn_win_kernel(const float* __restrict__ frame,
                    float* __restrict__ eucl_out)
{
    __shared__ __align__(16) unsigned char smem_raw[16384];
    float* sx = (float*)smem_raw;            // TILE floats
    float* sy = sx + TILE;
    float* sz = sy + TILE;
    int*   soi = (int*)(sz + TILE);          // TILE ints

    const int tid   = threadIdx.x;
    const int h     = tid & 1;
    const int slot  = tid >> 1;              // 0..63
    const int b     = blockIdx.x >> 6;       // batch
    const int chunk = blockIdx.x & 63;
    const int p     = chunk * QPB + slot;    // sorted position of my query
    const int t_own = (chunk * QPB) / TILE;

    const float* xs = g_xs + b * NL;
    const float* ys = g_ys + b * NL;
    const float* zs = g_zs + b * NL;
    const int*   oi = g_oi + b * NL;

    const float cx = xs[p], cy = ys[p], cz = zs[p];
    const int   q  = oi[p];
    const unsigned long long ncx2 = pack2(-cx, -cx);
    const unsigned long long ncy2 = pack2(-cy, -cy);
    const unsigned long long ncz2 = pack2(-cz, -cz);

    unsigned long long ks[NK];
#pragma unroll
    for (int i = 0; i < NK; ++i) ks[i] = INF_KEY;

    float2 lbuf[BCAP];
    int    cnt  = 0;
    float  taud = __uint_as_float(0x7F800000u);   // +inf

    const float4* x4 = (const float4*)sx;
    const float4* y4 = (const float4*)sy;
    const float4* z4 = (const float4*)sz;

    // tile visit order: own first, then by proximity
    const int offs[7] = {0, -1, 1, -2, 2, -3, 3};

#pragma unroll 1
    for (int oidx = 0; oidx < 7; ++oidx) {
        const int t = t_own + offs[oidx];
        if (t < 0 || t >= NTILES) continue;

        if (oidx > 0) {
            // block vote: does any query still need this tile?
            const float xlo = xs[t * TILE];
            const float xhi = xs[t * TILE + TILE - 1];
            // per-query tau (conservative: min of the pair's 16th-dists)
            float tq = __uint_as_float((unsigned)(ks[NK - 1] >> 32));
            tq = fminf(tq, __shfl_xor_sync(0xffffffffu, tq, 1));
            const float gap = fmaxf(0.f, fmaxf(__fadd_rn(xlo, -cx),
                                               __fadd_rn(cx, -xhi)));
            const int need = (__fmul_rn(gap, gap) <= tq);
            if (!__syncthreads_or(need)) continue;
        }

        // ---- stage tile t ----
        __syncthreads();
        {
            const int tb = t * TILE;
            for (int i = tid; i < TILE; i += TPB) {
                sx[i]  = xs[tb + i];
                sy[i]  = ys[tb + i];
                sz[i]  = zs[tb + i];
                soi[i] = oi[tb + i];
            }
        }
        __syncthreads();

        // ---- scan tile (R6 inner economics, tile-local j) ----
#pragma unroll 2
        for (int m = 0; m < TILE / 16; ++m) {
            const int g0 = 4 * m + 2 * h;
            float4 xa = x4[g0], xb = x4[g0 + 1];
            float4 ya = y4[g0], yb = y4[g0 + 1];
            float4 za = z4[g0], zb = z4[g0 + 1];

            float d0, d1, d2, d3, d4, d5, d6, d7;
            dist2(pack2(xa.x, xa.y), pack2(ya.x, ya.y), pack2(za.x, za.y),
                  ncx2, ncy2, ncz2, d0, d1);
            dist2(pack2(xa.z, xa.w), pack2(ya.z, ya.w), pack2(za.z, za.w),
                  ncx2, ncy2, ncz2, d2, d3);
            dist2(pack2(xb.x, xb.y), pack2(yb.x, yb.y), pack2(zb.x, zb.y),
                  ncx2, ncy2, ncz2, d4, d5);
            dist2(pack2(xb.z, xb.w), pack2(yb.z, yb.w), pack2(zb.z, zb.w),
                  ncx2, ncy2, ncz2, d6, d7);

            const int j0 = 16 * m + 8 * h;   // tile-local candidate index
            if (d0 <= taud) { lbuf[cnt] = make_float2(d0, __int_as_float(j0));     cnt++; }
            if (d1 <= taud) { lbuf[cnt] = make_float2(d1, __int_as_float(j0 + 1)); cnt++; }
            if (d2 <= taud) { lbuf[cnt] = make_float2(d2, __int_as_float(j0 + 2)); cnt++; }
            if (d3 <= taud) { lbuf[cnt] = make_float2(d3, __int_as_float(j0 + 3)); cnt++; }
            if (d4 <= taud) { lbuf[cnt] = make_float2(d4, __int_as_float(j0 + 4)); cnt++; }
            if (d5 <= taud) { lbuf[cnt] = make_float2(d5, __int_as_float(j0 + 5)); cnt++; }
            if (d6 <= taud) { lbuf[cnt] = make_float2(d6, __int_as_float(j0 + 6)); cnt++; }
            if (d7 <= taud) { lbuf[cnt] = make_float2(d7, __int_as_float(j0 + 7)); cnt++; }

            if (__any_sync(0xffffffffu, cnt > BCAP - 8)) {
                for (int i = 0; i < cnt; ++i) {
                    const unsigned long long nk =
                        ((unsigned long long)__float_as_uint(lbuf[i].x) << 32)
                        | (unsigned)soi[__float_as_int(lbuf[i].y)];
                    if (nk < ks[NK - 1]) kins(ks, nk);
                }
                cnt  = 0;
                taud = __uint_as_float((unsigned)(ks[NK - 1] >> 32));
            }
        }

        // ---- end-of-tile flush (soi still resident) ----
        for (int i = 0; i < cnt; ++i) {
            const unsigned long long nk =
                ((unsigned long long)__float_as_uint(lbuf[i].x) << 32)
                | (unsigned)soi[__float_as_int(lbuf[i].y)];
            if (nk < ks[NK - 1]) kins(ks, nk);
        }
        cnt  = 0;
        taud = __uint_as_float((unsigned)(ks[NK - 1] >> 32));
    }

    // -------- exact 2-way merge of the pair's lists -----------------------
    __syncthreads();
    unsigned long long* mk = (unsigned long long*)smem_raw;   // 128*16 = 16KB
#pragma unroll
    for (int k = 0; k < NK; ++k) mk[tid * NK + k] = ks[k];
    __syncthreads();

    if (h == 0) {
        const unsigned long long* L = mk + tid * NK;   // lists tid, tid+1
        int ia = 0, ib = 0;
        unsigned long long fin[NK];
#pragma unroll
        for (int k = 0; k < NK; ++k) {
            unsigned long long k0 = L[ia];
            unsigned long long k1 = L[NK + ib];
            bool ta = (k0 < k1);
            fin[k] = ta ? k0 : k1;
            if (ta) ia++; else ib++;
        }

        // outputs
        const float* fq = frame + ((size_t)b * NL + q) * 12;
        float R[3][3];
#pragma unroll
        for (int c = 0; c < 3; c++)
#pragma unroll
            for (int r = 0; r < 3; r++)
                R[c][r] = fq[3 + c * 3 + r];

        const size_t base = ((size_t)b * NL + q) * NK;
        int4* nb4 = (int4*)(g_nbr + base);
#pragma unroll
        for (int kk = 0; kk < 4; ++kk)
            nb4[kk] = make_int4((int)(unsigned)fin[4 * kk],
                                (int)(unsigned)fin[4 * kk + 1],
                                (int)(unsigned)fin[4 * kk + 2],
                                (int)(unsigned)fin[4 * kk + 3]);

        float4* eo = (float4*)(eucl_out + base * 3);
#pragma unroll
        for (int kk = 0; kk < 4; ++kk) {
            float e[12];
#pragma unroll
            for (int u = 0; u < 4; ++u) {
                const int n = (int)(unsigned)fin[4 * kk + u];
                const float* fn = frame + ((size_t)b * NL + n) * 12;
                float dd0 = fn[0] - cx;
                float dd1 = fn[1] - cy;
                float dd2 = fn[2] - cz;
                e[3 * u + 0] = dd0 * R[0][0] + dd1 * R[1][0] + dd2 * R[2][0];
                e[3 * u + 1] = dd0 * R[0][1] + dd1 * R[1][1] + dd2 * R[2][1];
                e[3 * u + 2] = dd0 * R[0][2] + dd1 * R[1][2] + dd2 * R[2][2];
            }
            eo[3 * kk + 0] = make_float4(e[0], e[1], e[2],  e[3]);
            eo[3 * kk + 1] = make_float4(e[4], e[5], e[6],  e[7]);
            eo[3 * kk + 2] = make_float4(e[8], e[9], e[10], e[11]);
        }
    }
}

// ---------------------------------------------------------------------------
// Kernel 2: attribute gather (measured-best config, ~44us = store ceiling).
// ---------------------------------------------------------------------------
__global__ __launch_bounds__(256, 8)
void gather_kernel(const float* __restrict__ attr,
                   float* __restrict__ gout)
{
    const int warp = (blockIdx.x * 256 + threadIdx.x) >> 5;
    const int lane = threadIdx.x & 31;
    const int row  = warp * 4 + (lane >> 3);
    const int l8   = lane & 7;

    const int b = row / (NL * NK);
    const int n = g_nbr[row];

    const float4* src = (const float4*)(attr + ((size_t)b * NL + n) * ND);
    float4*       dst = (float4*)(gout + (size_t)row * ND);

    float4 v0 = src[l8];
    float4 v1 = src[l8 + 8];
    float4 v2 = src[l8 + 16];
    float4 v3 = src[l8 + 24];
    dst[l8]      = v0;
    dst[l8 + 8]  = v1;
    dst[l8 + 16] = v2;
    dst[l8 + 24] = v3;
}

extern "C" void kernel_launch(void* const* d_in, const int* in_sizes, int n_in,
                              void* d_out, int out_size)
{
    const float* frame = (const float*)d_in[0];
    const float* attr  = (const float*)d_in[1];
    if (in_sizes[0] != NB * NL * 12) {
        frame = (const float*)d_in[1];
        attr  = (const float*)d_in[0];
    }

    float* eucl = (float*)d_out;
    float* gath = (float*)d_out + (size_t)NB * NL * NK * 3;

    sort_kernel<<<NB, 1024>>>(frame);

    knn_win_kernel<<<NB * 64, TPB>>>(frame, eucl);        // 512 blocks

    const int rows = NB * NL * NK;
    gather_kernel<<<rows / 32, 256>>>(attr, gath);
}

// round 15
// speedup vs baseline: 3.8754x; 1.5820x over previous
#include <cuda_runtime.h>

#define NB 8
#define NL 4096
#define NK 16
#define ND 128

#define QPB 64            // queries per block (sorted-consecutive)
#define TPB 128           // 2 threads per query
#define TILE_S 256        // candidate tile (sorted-x slab)
#define NTILES_S (NL / TILE_S)
#define BCAP 24           // per-thread candidate buffer capacity

// scratch (allocation-free rule -> __device__ globals)
__device__ int   g_nbr[NB * NL * NK];
__device__ float g_xs[NB * NL];
__device__ float g_ys[NB * NL];
__device__ float g_zs[NB * NL];
__device__ int   g_oi[NB * NL];

#define INF_KEY 0x7F800000FFFFFFFFull   // (+inf dist, max idx)

// ---------------------------------------------------------------------------
// u64-key top-16 insert (sorted ascending, median split). Key =
// (dist_bits<<32)|orig_idx: unsigned compare = exact lexicographic (d, idx)
// = jax.lax.top_k order. Order-independent.
// ---------------------------------------------------------------------------
__device__ __forceinline__ void kins(unsigned long long (&ks)[NK],
                                     unsigned long long nk)
{
    if (nk < ks[7]) {
#pragma unroll
        for (int i = 15; i > 8; --i) ks[i] = ks[i - 1];
        ks[8] = ks[7];
        unsigned long long c = nk;
#pragma unroll
        for (int i = 0; i < 8; ++i) {
            if (c < ks[i]) { unsigned long long t = ks[i]; ks[i] = c; c = t; }
        }
    } else {
        unsigned long long c = nk;
#pragma unroll
        for (int i = 8; i < 16; ++i) {
            if (c < ks[i]) { unsigned long long t = ks[i]; ks[i] = c; c = t; }
        }
    }
}

__device__ __forceinline__ unsigned long long pack2(float lo, float hi)
{
    unsigned long long r;
    asm("mov.b64 %0, {%1, %2};" : "=l"(r) : "f"(lo), "f"(hi));
    return r;
}

// packed squared-distance for one PAIR (exact unfused IEEE rn per lane)
__device__ __forceinline__ void dist2(unsigned long long x2, unsigned long long y2,
                                      unsigned long long z2,
                                      unsigned long long ncx2, unsigned long long ncy2,
                                      unsigned long long ncz2,
                                      float& d0, float& d1)
{
    unsigned long long dx2, dy2, dz2, m0, m1, m2, s0, dd;
    asm("add.rn.f32x2 %0, %1, %2;" : "=l"(dx2) : "l"(x2), "l"(ncx2));
    asm("add.rn.f32x2 %0, %1, %2;" : "=l"(dy2) : "l"(y2), "l"(ncy2));
    asm("add.rn.f32x2 %0, %1, %2;" : "=l"(dz2) : "l"(z2), "l"(ncz2));
    asm("mul.rn.f32x2 %0, %1, %2;" : "=l"(m0) : "l"(dx2), "l"(dx2));
    asm("mul.rn.f32x2 %0, %1, %2;" : "=l"(m1) : "l"(dy2), "l"(dy2));
    asm("mul.rn.f32x2 %0, %1, %2;" : "=l"(m2) : "l"(dz2), "l"(dz2));
    asm("add.rn.f32x2 %0, %1, %2;" : "=l"(s0) : "l"(m0), "l"(m1));
    asm("add.rn.f32x2 %0, %1, %2;" : "=l"(dd) : "l"(s0), "l"(m2));
    asm("mov.b64 {%0, %1}, %2;" : "=f"(d0), "=f"(d1) : "l"(dd));
}

// ---------------------------------------------------------------------------
// Kernel 0: per-batch bitonic sort of (x, idx) -> sorted SoA arrays (proven).
// ---------------------------------------------------------------------------
__global__ __launch_bounds__(1024)
void sort_kernel(const float* __restrict__ frame)
{
    __shared__ unsigned long long sk[NL];
    const int b   = blockIdx.x;
    const int tid = threadIdx.x;
    const float* fb = frame + (size_t)b * NL * 12;

    for (int i = tid; i < NL; i += 1024) {
        unsigned fbits = __float_as_uint(fb[(size_t)i * 12]);
        unsigned m = fbits ^ ((unsigned)((int)fbits >> 31) | 0x80000000u);
        sk[i] = ((unsigned long long)m << 32) | (unsigned)i;
    }
    __syncthreads();

    for (int k = 2; k <= NL; k <<= 1) {
        for (int j = k >> 1; j > 0; j >>= 1) {
            for (int i = tid; i < NL; i += 1024) {
                const int ixj = i ^ j;
                if (ixj > i) {
                    unsigned long long a = sk[i], c = sk[ixj];
                    const bool up = ((i & k) == 0);
                    if ((a > c) == up) { sk[i] = c; sk[ixj] = a; }
                }
            }
            __syncthreads();
        }
    }

    for (int i = tid; i < NL; i += 1024) {
        const int oi = (int)(unsigned)sk[i];
        const float* p = fb + (size_t)oi * 12;
        g_xs[b * NL + i] = p[0];
        g_ys[b * NL + i] = p[1];
        g_zs[b * NL + i] = p[2];
        g_oi[b * NL + i] = oi;
    }
}

// ---------------------------------------------------------------------------
// scan one 256-tile with R6 inner economics (called with uniform control)
// ---------------------------------------------------------------------------
struct ScanCtx {
    unsigned long long ncx2, ncy2, ncz2;
    int tid, h;
};

__device__ __forceinline__ void scan_tile(
    int t, const float* xs, const float* ys, const float* zs, const int* oi,
    float* sx, float* sy, float* sz, int* soi,
    const ScanCtx& c, unsigned long long (&ks)[NK],
    float2* lbuf, int& cnt, float& taud)
{
    __syncthreads();
    {
        const int tb = t * TILE_S;
        for (int i = c.tid; i < TILE_S; i += TPB) {
            sx[i]  = xs[tb + i];
            sy[i]  = ys[tb + i];
            sz[i]  = zs[tb + i];
            soi[i] = oi[tb + i];
        }
    }
    __syncthreads();

    const float4* x4 = (const float4*)sx;
    const float4* y4 = (const float4*)sy;
    const float4* z4 = (const float4*)sz;

#pragma unroll 2
    for (int m = 0; m < TILE_S / 16; ++m) {
        const int g0 = 4 * m + 2 * c.h;
        float4 xa = x4[g0], xb = x4[g0 + 1];
        float4 ya = y4[g0], yb = y4[g0 + 1];
        float4 za = z4[g0], zb = z4[g0 + 1];

        float d0, d1, d2, d3, d4, d5, d6, d7;
        dist2(pack2(xa.x, xa.y), pack2(ya.x, ya.y), pack2(za.x, za.y),
              c.ncx2, c.ncy2, c.ncz2, d0, d1);
        dist2(pack2(xa.z, xa.w), pack2(ya.z, ya.w), pack2(za.z, za.w),
              c.ncx2, c.ncy2, c.ncz2, d2, d3);
        dist2(pack2(xb.x, xb.y), pack2(yb.x, yb.y), pack2(zb.x, zb.y),
              c.ncx2, c.ncy2, c.ncz2, d4, d5);
        dist2(pack2(xb.z, xb.w), pack2(yb.z, yb.w), pack2(zb.z, zb.w),
              c.ncx2, c.ncy2, c.ncz2, d6, d7);

        const int j0 = 16 * m + 8 * c.h;     // tile-local index
        if (d0 <= taud) { lbuf[cnt] = make_float2(d0, __int_as_float(j0));     cnt++; }
        if (d1 <= taud) { lbuf[cnt] = make_float2(d1, __int_as_float(j0 + 1)); cnt++; }
        if (d2 <= taud) { lbuf[cnt] = make_float2(d2, __int_as_float(j0 + 2)); cnt++; }
        if (d3 <= taud) { lbuf[cnt] = make_float2(d3, __int_as_float(j0 + 3)); cnt++; }
        if (d4 <= taud) { lbuf[cnt] = make_float2(d4, __int_as_float(j0 + 4)); cnt++; }
        if (d5 <= taud) { lbuf[cnt] = make_float2(d5, __int_as_float(j0 + 5)); cnt++; }
        if (d6 <= taud) { lbuf[cnt] = make_float2(d6, __int_as_float(j0 + 6)); cnt++; }
        if (d7 <= taud) { lbuf[cnt] = make_float2(d7, __int_as_float(j0 + 7)); cnt++; }

        if (__any_sync(0xffffffffu, cnt > BCAP - 8)) {
            for (int i = 0; i < cnt; ++i) {
                const unsigned long long nk =
                    ((unsigned long long)__float_as_uint(lbuf[i].x) << 32)
                    | (unsigned)soi[__float_as_int(lbuf[i].y)];
                if (nk < ks[NK - 1]) kins(ks, nk);
            }
            cnt  = 0;
            taud = fminf(taud, __uint_as_float((unsigned)(ks[NK - 1] >> 32)));
        }
    }

    // end-of-tile flush (soi still resident) + tau refresh
    for (int i = 0; i < cnt; ++i) {
        const unsigned long long nk =
            ((unsigned long long)__float_as_uint(lbuf[i].x) << 32)
            | (unsigned)soi[__float_as_int(lbuf[i].y)];
        if (nk < ks[NK - 1]) kins(ks, nk);
    }
    cnt  = 0;
    taud = fminf(taud, __uint_as_float((unsigned)(ks[NK - 1] >> 32)));
}

// block-uniform vote: does any query still need tile t?
__device__ __forceinline__ bool tile_vote(
    int t, const float* xs, float cx, float taud)
{
    float tq = fminf(taud, __shfl_xor_sync(0xffffffffu, taud, 1));
    const float xlo = xs[t * TILE_S];
    const float xhi = xs[t * TILE_S + TILE_S - 1];
    const float gap = fmaxf(0.f, fmaxf(__fadd_rn(xlo, -cx),
                                       __fadd_rn(cx, -xhi)));
    // 1+2e-6 inflation: ULP-conservative (only ever causes extra scans)
    const int need = (__fmul_rn(gap, gap) <= tq * 1.000002f);
    return __syncthreads_or(need);
}

// ---------------------------------------------------------------------------
// Kernel 1: exact 16-NN, tau-seeded tile-windowed scan.
// ---------------------------------------------------------------------------
__global__ __launch_bounds__(TPB, 4)
void knn_win_kernel(const float* __restrict__ frame,
                    float* __restrict__ eucl_out)
{
    __shared__ __align__(16) unsigned char smem_raw[16384];
    float* sx  = (float*)smem_raw;           // TILE_S floats (1KB)
    float* sy  = sx + TILE_S;
    float* sz  = sy + TILE_S;
    int*   soi = (int*)(sz + TILE_S);

    const int tid   = threadIdx.x;
    const int h     = tid & 1;
    const int slot  = tid >> 1;              // 0..63
    const int b     = blockIdx.x >> 6;
    const int chunk = blockIdx.x & 63;
    const int p     = chunk * QPB + slot;    // sorted position of my query
    const int t_own = chunk >> 2;            // (chunk*64)/256

    const float* xs = g_xs + b * NL;
    const float* ys = g_ys + b * NL;
    const float* zs = g_zs + b * NL;
    const int*   oi = g_oi + b * NL;

    const float cx = xs[p], cy = ys[p], cz = zs[p];
    const int   q  = oi[p];

    ScanCtx ctx;
    ctx.ncx2 = pack2(-cx, -cx);
    ctx.ncy2 = pack2(-cy, -cy);
    ctx.ncz2 = pack2(-cz, -cz);
    ctx.tid = tid; ctx.h = h;

    unsigned long long ks[NK];
#pragma unroll
    for (int i = 0; i < NK; ++i) ks[i] = INF_KEY;

    float2 lbuf[BCAP];
    int    cnt = 0;

    // ---- tau seeding: 16 x-adjacent candidates give an upper bound -------
    float taud = 0.f;
    {
        int w0 = p - 8;
        if (w0 < 0) w0 = 0;
        if (w0 > NL - 16) w0 = NL - 16;
#pragma unroll
        for (int i = 0; i < 16; ++i) {
            const float dx = __fadd_rn(cx, -xs[w0 + i]);
            const float dy = __fadd_rn(cy, -ys[w0 + i]);
            const float dz = __fadd_rn(cz, -zs[w0 + i]);
            const float d  = __fadd_rn(__fadd_rn(__fmul_rn(dx, dx),
                                                 __fmul_rn(dy, dy)),
                                       __fmul_rn(dz, dz));
            taud = fmaxf(taud, d);
        }
    }

    // ---- own tile, then side-monotone expansion --------------------------
    scan_tile(t_own, xs, ys, zs, oi, sx, sy, sz, soi, ctx, ks, lbuf, cnt, taud);

    int  dl = 1, dr = 1;
    bool aliveL = (t_own - 1 >= 0);
    bool aliveR = (t_own + 1 < NTILES_S);
    while (aliveL || aliveR) {
        if (aliveL) {
            const int t = t_own - dl;
            if (tile_vote(t, xs, cx, taud)) {
                scan_tile(t, xs, ys, zs, oi, sx, sy, sz, soi, ctx, ks, lbuf, cnt, taud);
                dl++;
                aliveL = (t_own - dl >= 0);
            } else aliveL = false;
        }
        if (aliveR) {
            const int t = t_own + dr;
            if (tile_vote(t, xs, cx, taud)) {
                scan_tile(t, xs, ys, zs, oi, sx, sy, sz, soi, ctx, ks, lbuf, cnt, taud);
                dr++;
                aliveR = (t_own + dr < NTILES_S);
            } else aliveR = false;
        }
    }

    // -------- exact 2-way merge of the pair's lists -----------------------
    __syncthreads();
    unsigned long long* mk = (unsigned long long*)smem_raw;   // 128*16 = 16KB
#pragma unroll
    for (int k = 0; k < NK; ++k) mk[tid * NK + k] = ks[k];
    __syncthreads();

    if (h == 0) {
        const unsigned long long* L = mk + tid * NK;   // lists tid, tid+1
        int ia = 0, ib = 0;
        unsigned long long fin[NK];
#pragma unroll
        for (int k = 0; k < NK; ++k) {
            unsigned long long k0 = L[ia];
            unsigned long long k1 = L[NK + ib];
            bool ta = (k0 < k1);
            fin[k] = ta ? k0 : k1;
            if (ta) ia++; else ib++;
        }

        const float* fq = frame + ((size_t)b * NL + q) * 12;
        float R[3][3];
#pragma unroll
        for (int c = 0; c < 3; c++)
#pragma unroll
            for (int r = 0; r < 3; r++)
                R[c][r] = fq[3 + c * 3 + r];

        const size_t base = ((size_t)b * NL + q) * NK;
        int4* nb4 = (int4*)(g_nbr + base);
#pragma unroll
        for (int kk = 0; kk < 4; ++kk)
            nb4[kk] = make_int4((int)(unsigned)fin[4 * kk],
                                (int)(unsigned)fin[4 * kk + 1],
                                (int)(unsigned)fin[4 * kk + 2],
                                (int)(unsigned)fin[4 * kk + 3]);

        float4* eo = (float4*)(eucl_out + base * 3);
#pragma unroll
        for (int kk = 0; kk < 4; ++kk) {
            float e[12];
#pragma unroll
            for (int u = 0; u < 4; ++u) {
                const int n = (int)(unsigned)fin[4 * kk + u];
                const float* fn = frame + ((size_t)b * NL + n) * 12;
                float dd0 = fn[0] - cx;
                float dd1 = fn[1] - cy;
                float dd2 = fn[2] - cz;
                e[3 * u + 0] = dd0 * R[0][0] + dd1 * R[1][0] + dd2 * R[2][0];
                e[3 * u + 1] = dd0 * R[0][1] + dd1 * R[1][1] + dd2 * R[2][1];
                e[3 * u + 2] = dd0 * R[0][2] + dd1 * R[1][2] + dd2 * R[2][2];
            }
            eo[3 * kk + 0] = make_float4(e[0], e[1], e[2],  e[3]);
            eo[3 * kk + 1] = make_float4(e[4], e[5], e[6],  e[7]);
            eo[3 * kk + 2] = make_float4(e[8], e[9], e[10], e[11]);
        }
    }
}

// ---------------------------------------------------------------------------
// Kernel 2: attribute gather (measured-best config, ~44us = store ceiling).
// ---------------------------------------------------------------------------
__global__ __launch_bounds__(256, 8)
void gather_kernel(const float* __restrict__ attr,
                   float* __restrict__ gout)
{
    const int warp = (blockIdx.x * 256 + threadIdx.x) >> 5;
    const int lane = threadIdx.x & 31;
    const int row  = warp * 4 + (lane >> 3);
    const int l8   = lane & 7;

    const int b = row / (NL * NK);
    const int n = g_nbr[row];

    const float4* src = (const float4*)(attr + ((size_t)b * NL + n) * ND);
    float4*       dst = (float4*)(gout + (size_t)row * ND);

    float4 v0 = src[l8];
    float4 v1 = src[l8 + 8];
    float4 v2 = src[l8 + 16];
    float4 v3 = src[l8 + 24];
    dst[l8]      = v0;
    dst[l8 + 8]  = v1;
    dst[l8 + 16] = v2;
    dst[l8 + 24] = v3;
}

extern "C" void kernel_launch(void* const* d_in, const int* in_sizes, int n_in,
                              void* d_out, int out_size)
{
    const float* frame = (const float*)d_in[0];
    const float* attr  = (const float*)d_in[1];
    if (in_sizes[0] != NB * NL * 12) {
        frame = (const float*)d_in[1];
        attr  = (const float*)d_in[0];
    }

    float* eucl = (float*)d_out;
    float* gath = (float*)d_out + (size_t)NB * NL * NK * 3;

    sort_kernel<<<NB, 1024>>>(frame);

    knn_win_kernel<<<NB * 64, TPB>>>(frame, eucl);        // 512 blocks

    const int rows = NB * NL * NK;
    gather_kernel<<<rows / 32, 256>>>(attr, gath);
}